// round 15
// baseline (speedup 1.0000x reference)
#include <cuda_runtime.h>
#include <cuda_fp16.h>
#include <math.h>
#include <stdint.h>

// Problem constants
#define PV 32000
#define PKC 3
#define PD 1024
#define PS 2048
#define PB 2
#define PM (PS*PB)      // 4096
#define PK1 (PKC*PD)    // 3072

// ---------------------------------------------------------------------------
// Scratch (device globals)
// ---------------------------------------------------------------------------
__device__ __half   g_X[(size_t)PM * PK1];        // gathered ctx, fp16
__device__ __half   g_H[(size_t)PM * PD];         // hidden, fp16
__device__ uint32_t g_W1p[(size_t)(PK1/2) * PD];  // W1 k-pair-packed half2 [K/2][N]
__device__ uint32_t g_W2p[(size_t)(PD/2) * PV];   // W2 k-pair-packed half2 [K/2][N]

// ---------------------------------------------------------------------------
// helpers
// ---------------------------------------------------------------------------
__device__ __forceinline__ uint32_t smem_u32(const void* p) {
    uint32_t a;
    asm("{ .reg .u64 t; cvta.to.shared.u64 t, %1; cvt.u32.u64 %0, t; }" : "=r"(a) : "l"(p));
    return a;
}
__device__ __forceinline__ void cp_async16(uint32_t dst, const void* src) {
    asm volatile("cp.async.cg.shared.global [%0], [%1], 16;" :: "r"(dst), "l"(src));
}
__device__ __forceinline__ void cp_commit() { asm volatile("cp.async.commit_group;" ::: "memory"); }
template<int N> __device__ __forceinline__ void cp_wait() {
    asm volatile("cp.async.wait_group %0;" :: "n"(N) : "memory");
}
__device__ __forceinline__ void mma_f16(float* c, const uint32_t* a, const uint32_t* b) {
    asm volatile(
        "mma.sync.aligned.m16n8k16.row.col.f32.f16.f16.f32 "
        "{%0,%1,%2,%3}, {%4,%5,%6,%7}, {%8,%9}, {%0,%1,%2,%3};"
        : "+f"(c[0]), "+f"(c[1]), "+f"(c[2]), "+f"(c[3])
        : "r"(a[0]), "r"(a[1]), "r"(a[2]), "r"(a[3]), "r"(b[0]), "r"(b[1]));
}
__device__ __forceinline__ uint32_t pack2(float a, float b) {
    __half2 h = __halves2half2(__float2half(a), __float2half(b));   // low=a(k), high=b(k+1)
    return *reinterpret_cast<uint32_t*>(&h);
}

// ---------------------------------------------------------------------------
// Kernel 1: gather context embeddings -> fp16 X. grid (PM,PKC), 256 thr.
// Token dtype (int64 vs JAX-downcast int32) via parallel ballot (cheap).
// ---------------------------------------------------------------------------
__global__ void gather_ctx(const void* __restrict__ tokens, const float* __restrict__ emb) {
    const unsigned int* tw = (const unsigned int*)tokens;
    unsigned w = (threadIdx.x < 64 && (threadIdx.x & 1)) ? tw[threadIdx.x] : 0u;
    int any_hi = __syncthreads_or((int)(w != 0u));
    int is64 = !any_hi;

    int m = blockIdx.x, j = blockIdx.y;
    int t = m / PB, b = m - t * PB;
    int idx = t - PKC + j;
    long long tok = 0;
    if (idx >= 0) {
        size_t ofs = (size_t)idx * PB + b;
        tok = is64 ? ((const long long*)tokens)[ofs]
                   : (long long)((const int*)tokens)[ofs];
    }
    if (tok < 0) tok = 0;
    if (tok >= PV) tok = PV - 1;
    float4 f = reinterpret_cast<const float4*>(emb + (size_t)tok * PD)[threadIdx.x];
    __half h[4] = { __float2half(f.x), __float2half(f.y),
                    __float2half(f.z), __float2half(f.w) };
    *reinterpret_cast<uint2*>(g_X + (size_t)m * PK1 + (size_t)j * PD
                              + (size_t)threadIdx.x * 4) = *reinterpret_cast<uint2*>(h);
}

// ---------------------------------------------------------------------------
// Kernel 2: merged weight pack — W1 and W2 [K][N] fp32 -> half2 [K/2][N]
// ---------------------------------------------------------------------------
#define W1ROWS (PK1/2)   // 1536
#define W2ROWS (PD/2)    // 512
__global__ void pack_all(const float* __restrict__ W1, const float* __restrict__ W2,
                         uint32_t* __restrict__ B1, uint32_t* __restrict__ B2) {
    int y = blockIdx.y;
    const float* W; uint32_t* Bp; int Nd; size_t p;
    if (y < W1ROWS) { W = W1; Bp = B1; Nd = PD; p = (size_t)y; }
    else            { W = W2; Bp = B2; Nd = PV; p = (size_t)(y - W1ROWS); }

    int n4 = blockIdx.x * 256 + threadIdx.x;
    if (n4 >= (Nd >> 2)) return;
    const float4 r0 = *reinterpret_cast<const float4*>(W + (2 * p    ) * (size_t)Nd + n4 * 4);
    const float4 r1 = *reinterpret_cast<const float4*>(W + (2 * p + 1) * (size_t)Nd + n4 * 4);
    uint4 o;
    o.x = pack2(r0.x, r1.x); o.y = pack2(r0.y, r1.y);
    o.z = pack2(r0.z, r1.z); o.w = pack2(r0.w, r1.w);
    *reinterpret_cast<uint4*>(Bp + p * (size_t)Nd + n4 * 4) = o;
}

// ---------------------------------------------------------------------------
// fp16 mma.sync GEMM: CTA tile 128x256, BK=128, 2-stage cp.async,
// single barrier per iteration, 8 warps (2M x 4N), warp tile 64x64.
// Fragment loads DOUBLE-BUFFERED in registers: LDS(ks+1) overlaps HMMA(ks).
// A smem [128][136] halves; B smem [64][264] uint32 (half2 k-pairs).
// ---------------------------------------------------------------------------
#define BMT 128
#define BNT 256
#define BKT 128
#define APADH 136                         // halves per A smem row (128+8)
#define BPADW 264                         // uint32 per B smem row
#define A_BYTES (BMT*APADH*2)             // 34816
#define B_BYTES (64*BPADW*4)              // 67584
#define STG_BYTES (A_BYTES + B_BYTES)     // 102400
#define SMEM_BYTES (2 * STG_BYTES)        // 204800

__device__ __forceinline__ void issue_stage(
    uint32_t sm_base, int s, const __half* __restrict__ A, const uint32_t* __restrict__ Bp,
    int row0, int col0, int k0, int Kdim, int Ndim, int tid)
{
    uint32_t st = sm_base + (uint32_t)(s * STG_BYTES);
    // A: 128 rows x 128 halves = 2048 16B chunks (8/thread)
    #pragma unroll
    for (int j = 0; j < 8; j++) {
        int i = tid + j * 256;
        int row = i >> 4, c = i & 15;
        cp_async16(st + (uint32_t)(row * (APADH * 2) + c * 16),
                   A + (size_t)(row0 + row) * Kdim + k0 + c * 8);
    }
    // B: 64 pair-rows x 256 uint32 = 4096 16B chunks (16/thread)
    uint32_t stb = st + A_BYTES;
    int p0 = k0 >> 1;
    #pragma unroll
    for (int j = 0; j < 16; j++) {
        int i = tid + j * 256;
        int row = i >> 6, c = i & 63;
        cp_async16(stb + (uint32_t)((row * BPADW + c * 4) * 4),
                   Bp + (size_t)(p0 + row) * Ndim + col0 + c * 4);
    }
}

// load one k16-step's fragments into a register buffer
__device__ __forceinline__ void load_frags(
    const __half* As, const uint32_t* Bs, int ks,
    int wm, int wn, int gq, int tg,
    uint32_t af[4][4], uint32_t bf[8][2])
{
    #pragma unroll
    for (int mi = 0; mi < 4; mi++) {
        int m0 = wm * 64 + mi * 16 + gq;
        const __half* r0p = As + (size_t)m0 * APADH + ks * 16 + tg * 2;
        const __half* r1p = r0p + 8 * APADH;
        af[mi][0] = *reinterpret_cast<const uint32_t*>(r0p);
        af[mi][1] = *reinterpret_cast<const uint32_t*>(r1p);
        af[mi][2] = *reinterpret_cast<const uint32_t*>(r0p + 8);
        af[mi][3] = *reinterpret_cast<const uint32_t*>(r1p + 8);
    }
    #pragma unroll
    for (int ni = 0; ni < 8; ni++) {
        int n0 = wn * 64 + ni * 8 + gq;
        bf[ni][0] = Bs[(ks * 8 + tg    ) * BPADW + n0];
        bf[ni][1] = Bs[(ks * 8 + tg + 4) * BPADW + n0];
    }
}

template<int EPI>
__global__ __launch_bounds__(256, 1)
void mma_gemm(const __half* __restrict__ A, const uint32_t* __restrict__ Bp,
              const float* __restrict__ bias, void* __restrict__ Cv,
              int Ndim, int Kdim)
{
    extern __shared__ char smb[];
    const uint32_t sm_base = smem_u32(smb);

    const int tid = threadIdx.x;
    const int wid = tid >> 5, lane = tid & 31;
    const int wm = wid >> 2;             // 0..1 -> M offset wm*64
    const int wn = wid & 3;              // 0..3 -> N offset wn*64
    const int gq = lane >> 2;            // 0..7
    const int tg = lane & 3;             // 0..3

    const int row0 = blockIdx.x * BMT;
    const int col0 = blockIdx.y * BNT;
    const int NC = Kdim / BKT;

    float acc[4][8][4];
    #pragma unroll
    for (int mi = 0; mi < 4; mi++)
        #pragma unroll
        for (int ni = 0; ni < 8; ni++)
            #pragma unroll
            for (int q = 0; q < 4; q++) acc[mi][ni][q] = 0.0f;

    uint32_t af[2][4][4], bf[2][8][2];   // double-buffered fragments

    // prologue: stage 0
    issue_stage(sm_base, 0, A, Bp, row0, col0, 0, Kdim, Ndim, tid);
    cp_commit();

    for (int c = 0; c < NC; c++) {
        cp_wait<0>();                    // stage c complete (c+1 not yet issued)
        __syncthreads();                 // all warps done reading the other stage

        int nc = c + 1;
        if (nc < NC)
            issue_stage(sm_base, nc & 1, A, Bp, row0, col0, nc * BKT, Kdim, Ndim, tid);
        cp_commit();

        const __half* As = reinterpret_cast<const __half*>(smb + (c & 1) * STG_BYTES);
        const uint32_t* Bs = reinterpret_cast<const uint32_t*>(
            smb + (c & 1) * STG_BYTES + A_BYTES);

        // software-pipelined fragment loads: LDS(ks+1) overlaps HMMA(ks)
        load_frags(As, Bs, 0, wm, wn, gq, tg, af[0], bf[0]);
        #pragma unroll
        for (int ks = 0; ks < 8; ks++) {
            const int cur = ks & 1;
            if (ks < 7)
                load_frags(As, Bs, ks + 1, wm, wn, gq, tg, af[cur ^ 1], bf[cur ^ 1]);
            #pragma unroll
            for (int mi = 0; mi < 4; mi++)
                #pragma unroll
                for (int ni = 0; ni < 8; ni++)
                    mma_f16(acc[mi][ni], af[cur][mi], bf[cur][ni]);
        }
        // single barrier per iteration — next iteration's barrier protects reuse
    }

    // Epilogue
    #pragma unroll
    for (int mi = 0; mi < 4; mi++) {
        const int r0 = row0 + wm * 64 + mi * 16 + gq;
        #pragma unroll
        for (int ni = 0; ni < 8; ni++) {
            const int cl = col0 + wn * 64 + ni * 8 + 2 * tg;
            float bb0 = bias[cl], bb1 = bias[cl + 1];
            float v0 = acc[mi][ni][0] + bb0, v1 = acc[mi][ni][1] + bb1;
            float v2 = acc[mi][ni][2] + bb0, v3 = acc[mi][ni][3] + bb1;
            if (EPI == 0) {
                __half* C = (__half*)Cv;
                v0 = v0 / (1.0f + expf(-v0));
                v1 = v1 / (1.0f + expf(-v1));
                v2 = v2 / (1.0f + expf(-v2));
                v3 = v3 / (1.0f + expf(-v3));
                __half2 p0 = __halves2half2(__float2half(v0), __float2half(v1));
                __half2 p1 = __halves2half2(__float2half(v2), __float2half(v3));
                *reinterpret_cast<__half2*>(C + (size_t)r0 * Ndim + cl) = p0;
                *reinterpret_cast<__half2*>(C + (size_t)(r0 + 8) * Ndim + cl) = p1;
            } else {
                float* C = (float*)Cv;
                *reinterpret_cast<float2*>(C + (size_t)r0 * Ndim + cl) = make_float2(v0, v1);
                *reinterpret_cast<float2*>(C + (size_t)(r0 + 8) * Ndim + cl) = make_float2(v2, v3);
            }
        }
    }
}

// ---------------------------------------------------------------------------
extern "C" void kernel_launch(void* const* d_in, const int* in_sizes, int n_in,
                              void* d_out, int out_size) {
    const void*  tokens = d_in[0];
    const float* emb = (const float*)d_in[1];
    const float* W1  = (const float*)d_in[2];
    const float* b1  = (const float*)d_in[3];
    const float* W2  = (const float*)d_in[4];
    const float* b2  = (const float*)d_in[5];
    float* out = (float*)d_out;

    __half *pX, *pH; uint32_t *pW1p, *pW2p;
    cudaGetSymbolAddress((void**)&pX, g_X);
    cudaGetSymbolAddress((void**)&pH, g_H);
    cudaGetSymbolAddress((void**)&pW1p, g_W1p);
    cudaGetSymbolAddress((void**)&pW2p, g_W2p);

    cudaFuncSetAttribute(mma_gemm<0>, cudaFuncAttributeMaxDynamicSharedMemorySize, SMEM_BYTES);
    cudaFuncSetAttribute(mma_gemm<1>, cudaFuncAttributeMaxDynamicSharedMemorySize, SMEM_BYTES);

    // 4 launches: gather(+ballot dtype detect), pack_all, gemm0, gemm1.
    // gemm1 sits in the profiler's capture slot.
    gather_ctx<<<dim3(PM, PKC), 256>>>(tokens, emb);
    pack_all<<<dim3((PV / 4 + 255) / 256, W1ROWS + W2ROWS), 256>>>(W1, W2, pW1p, pW2p);
    // H = silu(X @ W1 + b1)   M=4096,N=1024,K=3072
    mma_gemm<0><<<dim3(PM / BMT, PD / BNT), 256, SMEM_BYTES>>>(pX, pW1p, b1, pH, PD, PK1);
    // out = H @ W2 + b2       M=4096,N=32000,K=1024
    mma_gemm<1><<<dim3(PM / BMT, PV / BNT), 256, SMEM_BYTES>>>(pH, pW2p, b2, out, PV, PD);
}

// round 16
// speedup vs baseline: 1.0623x; 1.0623x over previous
#include <cuda_runtime.h>
#include <cuda_fp16.h>
#include <math.h>
#include <stdint.h>

// Problem constants
#define PV 32000
#define PKC 3
#define PD 1024
#define PS 2048
#define PB 2
#define PM (PS*PB)      // 4096
#define PK1 (PKC*PD)    // 3072

// ---------------------------------------------------------------------------
// Scratch (device globals)
// ---------------------------------------------------------------------------
__device__ __half   g_X[(size_t)PM * PK1];        // gathered ctx, fp16
__device__ __half   g_H[(size_t)PM * PD];         // hidden, fp16
__device__ uint32_t g_W1p[(size_t)(PK1/2) * PD];  // W1 k-pair-packed half2 [K/2][N]
__device__ uint32_t g_W2p[(size_t)(PD/2) * PV];   // W2 k-pair-packed half2 [K/2][N]

// ---------------------------------------------------------------------------
// helpers
// ---------------------------------------------------------------------------
__device__ __forceinline__ uint32_t smem_u32(const void* p) {
    uint32_t a;
    asm("{ .reg .u64 t; cvta.to.shared.u64 t, %1; cvt.u32.u64 %0, t; }" : "=r"(a) : "l"(p));
    return a;
}
__device__ __forceinline__ void cp_async16(uint32_t dst, const void* src) {
    asm volatile("cp.async.cg.shared.global [%0], [%1], 16;" :: "r"(dst), "l"(src));
}
__device__ __forceinline__ void cp_commit() { asm volatile("cp.async.commit_group;" ::: "memory"); }
template<int N> __device__ __forceinline__ void cp_wait() {
    asm volatile("cp.async.wait_group %0;" :: "n"(N) : "memory");
}
__device__ __forceinline__ void mma_f16(float* c, const uint32_t* a, const uint32_t* b) {
    asm volatile(
        "mma.sync.aligned.m16n8k16.row.col.f32.f16.f16.f32 "
        "{%0,%1,%2,%3}, {%4,%5,%6,%7}, {%8,%9}, {%0,%1,%2,%3};"
        : "+f"(c[0]), "+f"(c[1]), "+f"(c[2]), "+f"(c[3])
        : "r"(a[0]), "r"(a[1]), "r"(a[2]), "r"(a[3]), "r"(b[0]), "r"(b[1]));
}
__device__ __forceinline__ uint32_t pack2(float a, float b) {
    __half2 h = __halves2half2(__float2half(a), __float2half(b));   // low=a(k), high=b(k+1)
    return *reinterpret_cast<uint32_t*>(&h);
}

// ---------------------------------------------------------------------------
// Fused prep kernel: one launch covers
//   [0, GATHER_BLOCKS)            : gather context embeddings -> fp16 X
//   [GATHER, GATHER+PACK1)        : pack W1 row (1 block per pair-row)
//   [GATHER+PACK1, total)         : pack W2 (32 blocks per pair-row)
// All jobs are DRAM-bound; fusing lets them share bandwidth concurrently.
// ---------------------------------------------------------------------------
#define GATHER_BLOCKS (PM * PKC)                        // 12288
#define PACK1_BLOCKS  (PK1 / 2)                         // 1536 (256 thr = 1024/4 cols)
#define PACK2_PERROW  ((PV / 4 + 255) / 256)            // 32
#define PACK2_BLOCKS  ((PD / 2) * PACK2_PERROW)         // 16384
#define PREP_BLOCKS   (GATHER_BLOCKS + PACK1_BLOCKS + PACK2_BLOCKS)  // 30208

__global__ void fused_prep(const void* __restrict__ tokens, const float* __restrict__ emb,
                           const float* __restrict__ W1, const float* __restrict__ W2) {
    int bid = blockIdx.x;
    int tid = threadIdx.x;

    if (bid < GATHER_BLOCKS) {
        // ---- gather: block = (m, j) ----
        const unsigned int* tw = (const unsigned int*)tokens;
        unsigned w = (tid < 64 && (tid & 1)) ? tw[tid] : 0u;
        int any_hi = __syncthreads_or((int)(w != 0u));
        int is64 = !any_hi;   // all-zero high words of first 32 int64 slots -> true int64

        int m = bid / PKC, j = bid - m * PKC;
        int t = m / PB, b = m - t * PB;
        int idx = t - PKC + j;
        long long tok = 0;
        if (idx >= 0) {
            size_t ofs = (size_t)idx * PB + b;
            tok = is64 ? ((const long long*)tokens)[ofs]
                       : (long long)((const int*)tokens)[ofs];
        }
        if (tok < 0) tok = 0;
        if (tok >= PV) tok = PV - 1;
        float4 f = reinterpret_cast<const float4*>(emb + (size_t)tok * PD)[tid];
        __half h[4] = { __float2half(f.x), __float2half(f.y),
                        __float2half(f.z), __float2half(f.w) };
        *reinterpret_cast<uint2*>(g_X + (size_t)m * PK1 + (size_t)j * PD
                                  + (size_t)tid * 4) = *reinterpret_cast<uint2*>(h);
        return;
    }
    bid -= GATHER_BLOCKS;

    const float* W; uint32_t* Bp; int Nd; size_t p; int n4;
    if (bid < PACK1_BLOCKS) {
        W = W1; Bp = g_W1p; Nd = PD; p = (size_t)bid; n4 = tid;
    } else {
        bid -= PACK1_BLOCKS;
        W = W2; Bp = g_W2p; Nd = PV;
        p = (size_t)(bid >> 5);                 // /PACK2_PERROW
        n4 = (bid & 31) * 256 + tid;
        if (n4 >= (PV >> 2)) return;
    }
    const float4 r0 = *reinterpret_cast<const float4*>(W + (2 * p    ) * (size_t)Nd + n4 * 4);
    const float4 r1 = *reinterpret_cast<const float4*>(W + (2 * p + 1) * (size_t)Nd + n4 * 4);
    uint4 o;
    o.x = pack2(r0.x, r1.x); o.y = pack2(r0.y, r1.y);
    o.z = pack2(r0.z, r1.z); o.w = pack2(r0.w, r1.w);
    *reinterpret_cast<uint4*>(Bp + p * (size_t)Nd + n4 * 4) = o;
}

// ---------------------------------------------------------------------------
// fp16 mma.sync GEMM (R10 champion config, byte-identical mainloop):
// CTA tile 128x256, BK=128, 2-stage cp.async, SINGLE barrier per iteration.
// 8 warps (2M x 4N), warp tile 64x64.
// A smem [128][136] halves; B smem [64][264] uint32 (half2 k-pairs).
// ---------------------------------------------------------------------------
#define BMT 128
#define BNT 256
#define BKT 128
#define APADH 136                         // halves per A smem row (128+8)
#define BPADW 264                         // uint32 per B smem row
#define A_BYTES (BMT*APADH*2)             // 34816
#define B_BYTES (64*BPADW*4)              // 67584
#define STG_BYTES (A_BYTES + B_BYTES)     // 102400
#define SMEM_BYTES (2 * STG_BYTES)        // 204800

__device__ __forceinline__ void issue_stage(
    uint32_t sm_base, int s, const __half* __restrict__ A, const uint32_t* __restrict__ Bp,
    int row0, int col0, int k0, int Kdim, int Ndim, int tid)
{
    uint32_t st = sm_base + (uint32_t)(s * STG_BYTES);
    // A: 128 rows x 128 halves = 2048 16B chunks (8/thread)
    #pragma unroll
    for (int j = 0; j < 8; j++) {
        int i = tid + j * 256;
        int row = i >> 4, c = i & 15;
        cp_async16(st + (uint32_t)(row * (APADH * 2) + c * 16),
                   A + (size_t)(row0 + row) * Kdim + k0 + c * 8);
    }
    // B: 64 pair-rows x 256 uint32 = 4096 16B chunks (16/thread)
    uint32_t stb = st + A_BYTES;
    int p0 = k0 >> 1;
    #pragma unroll
    for (int j = 0; j < 16; j++) {
        int i = tid + j * 256;
        int row = i >> 6, c = i & 63;
        cp_async16(stb + (uint32_t)((row * BPADW + c * 4) * 4),
                   Bp + (size_t)(p0 + row) * Ndim + col0 + c * 4);
    }
}

template<int EPI>
__global__ __launch_bounds__(256, 1)
void mma_gemm(const __half* __restrict__ A, const uint32_t* __restrict__ Bp,
              const float* __restrict__ bias, void* __restrict__ Cv,
              int Ndim, int Kdim)
{
    extern __shared__ char smb[];
    const uint32_t sm_base = smem_u32(smb);

    const int tid = threadIdx.x;
    const int wid = tid >> 5, lane = tid & 31;
    const int wm = wid >> 2;             // 0..1 -> M offset wm*64
    const int wn = wid & 3;              // 0..3 -> N offset wn*64
    const int gq = lane >> 2;            // 0..7
    const int tg = lane & 3;             // 0..3

    const int row0 = blockIdx.x * BMT;
    const int col0 = blockIdx.y * BNT;
    const int NC = Kdim / BKT;

    float acc[4][8][4];
    #pragma unroll
    for (int mi = 0; mi < 4; mi++)
        #pragma unroll
        for (int ni = 0; ni < 8; ni++)
            #pragma unroll
            for (int q = 0; q < 4; q++) acc[mi][ni][q] = 0.0f;

    // prologue: stage 0
    issue_stage(sm_base, 0, A, Bp, row0, col0, 0, Kdim, Ndim, tid);
    cp_commit();

    for (int c = 0; c < NC; c++) {
        cp_wait<0>();                    // stage c complete (c+1 not yet issued)
        __syncthreads();                 // all warps done reading the other stage

        int nc = c + 1;
        if (nc < NC)
            issue_stage(sm_base, nc & 1, A, Bp, row0, col0, nc * BKT, Kdim, Ndim, tid);
        cp_commit();

        const __half* As = reinterpret_cast<const __half*>(smb + (c & 1) * STG_BYTES);
        const uint32_t* Bs = reinterpret_cast<const uint32_t*>(
            smb + (c & 1) * STG_BYTES + A_BYTES);

        #pragma unroll
        for (int ks = 0; ks < 8; ks++) {          // eight k16 steps per chunk
            uint32_t af[4][4], bf[8][2];
            #pragma unroll
            for (int mi = 0; mi < 4; mi++) {
                int m0 = wm * 64 + mi * 16 + gq;
                const __half* r0p = As + (size_t)m0 * APADH + ks * 16 + tg * 2;
                const __half* r1p = r0p + 8 * APADH;
                af[mi][0] = *reinterpret_cast<const uint32_t*>(r0p);
                af[mi][1] = *reinterpret_cast<const uint32_t*>(r1p);
                af[mi][2] = *reinterpret_cast<const uint32_t*>(r0p + 8);
                af[mi][3] = *reinterpret_cast<const uint32_t*>(r1p + 8);
            }
            #pragma unroll
            for (int ni = 0; ni < 8; ni++) {
                int n0 = wn * 64 + ni * 8 + gq;
                bf[ni][0] = Bs[(ks * 8 + tg    ) * BPADW + n0];
                bf[ni][1] = Bs[(ks * 8 + tg + 4) * BPADW + n0];
            }
            #pragma unroll
            for (int mi = 0; mi < 4; mi++)
                #pragma unroll
                for (int ni = 0; ni < 8; ni++)
                    mma_f16(acc[mi][ni], af[mi], bf[ni]);
        }
        // single barrier per iteration — next iteration's barrier protects reuse
    }

    // Epilogue
    #pragma unroll
    for (int mi = 0; mi < 4; mi++) {
        const int r0 = row0 + wm * 64 + mi * 16 + gq;
        #pragma unroll
        for (int ni = 0; ni < 8; ni++) {
            const int cl = col0 + wn * 64 + ni * 8 + 2 * tg;
            float bb0 = bias[cl], bb1 = bias[cl + 1];
            float v0 = acc[mi][ni][0] + bb0, v1 = acc[mi][ni][1] + bb1;
            float v2 = acc[mi][ni][2] + bb0, v3 = acc[mi][ni][3] + bb1;
            if (EPI == 0) {
                __half* C = (__half*)Cv;
                v0 = v0 / (1.0f + expf(-v0));
                v1 = v1 / (1.0f + expf(-v1));
                v2 = v2 / (1.0f + expf(-v2));
                v3 = v3 / (1.0f + expf(-v3));
                __half2 p0 = __halves2half2(__float2half(v0), __float2half(v1));
                __half2 p1 = __halves2half2(__float2half(v2), __float2half(v3));
                *reinterpret_cast<__half2*>(C + (size_t)r0 * Ndim + cl) = p0;
                *reinterpret_cast<__half2*>(C + (size_t)(r0 + 8) * Ndim + cl) = p1;
            } else {
                float* C = (float*)Cv;
                *reinterpret_cast<float2*>(C + (size_t)r0 * Ndim + cl) = make_float2(v0, v1);
                *reinterpret_cast<float2*>(C + (size_t)(r0 + 8) * Ndim + cl) = make_float2(v2, v3);
            }
        }
    }
}

// ---------------------------------------------------------------------------
extern "C" void kernel_launch(void* const* d_in, const int* in_sizes, int n_in,
                              void* d_out, int out_size) {
    const void*  tokens = d_in[0];
    const float* emb = (const float*)d_in[1];
    const float* W1  = (const float*)d_in[2];
    const float* b1  = (const float*)d_in[3];
    const float* W2  = (const float*)d_in[4];
    const float* b2  = (const float*)d_in[5];
    float* out = (float*)d_out;

    __half *pX, *pH; uint32_t *pW1p, *pW2p;
    cudaGetSymbolAddress((void**)&pX, g_X);
    cudaGetSymbolAddress((void**)&pH, g_H);
    cudaGetSymbolAddress((void**)&pW1p, g_W1p);
    cudaGetSymbolAddress((void**)&pW2p, g_W2p);

    cudaFuncSetAttribute(mma_gemm<0>, cudaFuncAttributeMaxDynamicSharedMemorySize, SMEM_BYTES);
    cudaFuncSetAttribute(mma_gemm<1>, cudaFuncAttributeMaxDynamicSharedMemorySize, SMEM_BYTES);

    // 3 launches: fused prep (gather + dtype detect + both weight packs),
    // then the two GEMMs.
    fused_prep<<<PREP_BLOCKS, 256>>>(tokens, emb, W1, W2);
    // H = silu(X @ W1 + b1)   M=4096,N=1024,K=3072
    mma_gemm<0><<<dim3(PM / BMT, PD / BNT), 256, SMEM_BYTES>>>(pX, pW1p, b1, pH, PD, PK1);
    // out = H @ W2 + b2       M=4096,N=32000,K=1024
    mma_gemm<1><<<dim3(PM / BMT, PV / BNT), 256, SMEM_BYTES>>>(pH, pW2p, b2, out, PV, PD);
}